// round 1
// baseline (speedup 1.0000x reference)
#include <cuda_runtime.h>
#include <cuda_bf16.h>
#include <math.h>

#define BATCH 32
#define NUM_HEADS 16
#define HEAD_DIM 64
#define HIDDEN 1024
#define T_CACHED 2047
#define T_OUT 2048
#define SCALE 0.125f   // 64^-0.5

// ---------------- device scratch (no allocations allowed) ----------------
__device__ __align__(16) float g_qkv[BATCH * 3 * HIDDEN];   // [32, 3072]
__device__ __align__(16) float g_attn[BATCH * HIDDEN];      // [32, 1024] head outputs

// ---------------- init: qkv <- b_attn broadcast, out_attn <- b_proj ----------------
__global__ void init_kernel(const float* __restrict__ b_attn,
                            const float* __restrict__ b_proj,
                            float* __restrict__ out_attn) {
    int i = blockIdx.x * 256 + threadIdx.x;
    if (i < BATCH * 3 * HIDDEN) g_qkv[i] = b_attn[i % (3 * HIDDEN)];
    if (i < BATCH * HIDDEN)     out_attn[i] = b_proj[i % HIDDEN];
}

// ---------------- small GEMM: out[32,N] += X[32,K] @ W[K,N] ----------------
// grid: (N/128, CHUNKS). Each thread owns one output column j and 32 batch accumulators.
// K-dim split over blockIdx.y; partials merged with atomicAdd into bias-preloaded out.
__global__ void gemm32_kernel(const float* __restrict__ X,
                              const float* __restrict__ W,
                              float* __restrict__ out,
                              int K, int N) {
    int j = blockIdx.x * 128 + threadIdx.x;
    int chunk = K / gridDim.y;
    int h0 = blockIdx.y * chunk;

    __shared__ float xs[BATCH * 64];
    float acc[BATCH];
#pragma unroll
    for (int b = 0; b < BATCH; b++) acc[b] = 0.f;

    for (int hh0 = h0; hh0 < h0 + chunk; hh0 += 64) {
        // stage X chunk [32][64] into smem
        for (int i = threadIdx.x; i < BATCH * 64; i += 128) {
            int b = i >> 6, hh = i & 63;
            xs[i] = X[b * K + hh0 + hh];
        }
        __syncthreads();
#pragma unroll 4
        for (int hh = 0; hh < 64; hh++) {
            float w = W[(size_t)(hh0 + hh) * N + j];
#pragma unroll
            for (int b = 0; b < BATCH; b++)
                acc[b] = fmaf(xs[b * 64 + hh], w, acc[b]);
        }
        __syncthreads();
    }
#pragma unroll
    for (int b = 0; b < BATCH; b++)
        atomicAdd(&out[b * N + j], acc[b]);
}

// ---------------- fused KV-concat + single-query attention ----------------
// One block per (batch, head). 256 threads: 16 groups x 16 lanes.
// Each lane handles 4 contiguous floats (float4) of a 64-float row.
__global__ __launch_bounds__(256, 4)
void attn_kernel(const float* __restrict__ key_cache,
                 const float* __restrict__ value_cache,
                 const int* __restrict__ seq_lens,
                 float* __restrict__ Kout,
                 float* __restrict__ Vout) {
    const int bh = blockIdx.x;
    const int b = bh >> 4;
    const int h = bh & 15;
    const int tid = threadIdx.x;
    const int grp = tid >> 4;     // 0..15 : row group
    const int lane = tid & 15;    // 0..15 : float4 lane within row

    __shared__ float sc[T_OUT];          // scores / probs
    __shared__ float qs[HEAD_DIM];
    __shared__ float wred[8];
    __shared__ __align__(16) float red[16 * HEAD_DIM]; // per-group V partials

    const int seq_len = seq_lens[b];

    if (tid < HEAD_DIM)
        qs[tid] = g_qkv[b * 3072 + h * HEAD_DIM + tid] * SCALE;
    __syncthreads();

    const float4 q4 = ((const float4*)qs)[lane];

    const size_t base_c = (size_t)bh * T_CACHED * HEAD_DIM;
    const size_t base_o = (size_t)bh * T_OUT * HEAD_DIM;
    const float4* kc4 = (const float4*)(key_cache + base_c);
    const float4* vc4 = (const float4*)(value_cache + base_c);
    float4* Ko4 = (float4*)(Kout + base_o);
    float4* Vo4 = (float4*)(Vout + base_o);

    const float4 knew = ((const float4*)(g_qkv + b * 3072 + HIDDEN + h * HEAD_DIM))[lane];
    const float4 vnew = ((const float4*)(g_qkv + b * 3072 + 2 * HIDDEN + h * HEAD_DIM))[lane];

    // ---- pass 1: stream K rows: copy to output + compute masked scores ----
#pragma unroll 2
    for (int t = grp; t < T_OUT; t += 16) {
        float4 kv = (t < T_CACHED) ? kc4[(size_t)t * 16 + lane] : knew;
        Ko4[(size_t)t * 16 + lane] = kv;
        float p = kv.x * q4.x + kv.y * q4.y + kv.z * q4.z + kv.w * q4.w;
        p += __shfl_xor_sync(0xffffffffu, p, 1);
        p += __shfl_xor_sync(0xffffffffu, p, 2);
        p += __shfl_xor_sync(0xffffffffu, p, 4);
        p += __shfl_xor_sync(0xffffffffu, p, 8);
        if (lane == 0) {
            bool valid = (t < seq_len) || (t == T_OUT - 1);
            sc[t] = valid ? p : -1e30f;
        }
    }
    __syncthreads();

    // ---- softmax over sc[0..2047] ----
    float m = -1e30f;
    for (int t = tid; t < T_OUT; t += 256) m = fmaxf(m, sc[t]);
#pragma unroll
    for (int o = 16; o > 0; o >>= 1) m = fmaxf(m, __shfl_xor_sync(0xffffffffu, m, o));
    if ((tid & 31) == 0) wred[tid >> 5] = m;
    __syncthreads();
    m = fmaxf(fmaxf(fmaxf(wred[0], wred[1]), fmaxf(wred[2], wred[3])),
              fmaxf(fmaxf(wred[4], wred[5]), fmaxf(wred[6], wred[7])));
    __syncthreads();

    float s = 0.f;
    for (int t = tid; t < T_OUT; t += 256) {
        float e = __expf(sc[t] - m);
        sc[t] = e;
        s += e;
    }
#pragma unroll
    for (int o = 16; o > 0; o >>= 1) s += __shfl_xor_sync(0xffffffffu, s, o);
    if ((tid & 31) == 0) wred[tid >> 5] = s;
    __syncthreads();
    s = (wred[0] + wred[1]) + (wred[2] + wred[3]) + (wred[4] + wred[5]) + (wred[6] + wred[7]);
    const float inv = 1.f / s;

    // ---- pass 2: stream V rows: copy to output + weighted accumulation ----
    float4 acc = make_float4(0.f, 0.f, 0.f, 0.f);
#pragma unroll 2
    for (int t = grp; t < T_OUT; t += 16) {
        float4 vv = (t < T_CACHED) ? vc4[(size_t)t * 16 + lane] : vnew;
        Vo4[(size_t)t * 16 + lane] = vv;
        float p = sc[t] * inv;
        acc.x = fmaf(p, vv.x, acc.x);
        acc.y = fmaf(p, vv.y, acc.y);
        acc.z = fmaf(p, vv.z, acc.z);
        acc.w = fmaf(p, vv.w, acc.w);
    }

    // reduce the 16 group partials
    float4* red4 = (float4*)red;
    red4[grp * 16 + lane] = acc;
    __syncthreads();
    if (tid < 16) {
        float4 tot = make_float4(0.f, 0.f, 0.f, 0.f);
#pragma unroll
        for (int g = 0; g < 16; g++) {
            float4 r = red4[g * 16 + tid];
            tot.x += r.x; tot.y += r.y; tot.z += r.z; tot.w += r.w;
        }
        ((float4*)(g_attn + b * HIDDEN + h * HEAD_DIM))[tid] = tot;
    }
}

// ---------------- launch ----------------
extern "C" void kernel_launch(void* const* d_in, const int* in_sizes, int n_in,
                              void* d_out, int out_size) {
    int idx = 0;
    const float* hs       = (const float*)d_in[idx++];   // [32,1,1024]
    const float* kc       = (const float*)d_in[idx++];   // [32,16,2047,64]
    const float* vc       = (const float*)d_in[idx++];   // [32,16,2047,64]
    idx++;                                               // block_tables (unused)
    const int*   seq_lens = (const int*)d_in[idx++];     // [32]
    if (idx < n_in && in_sizes[idx] == 1) idx++;         // max_seq_len scalar, if present
    const float* W_attn   = (const float*)d_in[idx++];   // [1024,3072]
    const float* b_attn   = (const float*)d_in[idx++];   // [3072]
    const float* W_proj   = (const float*)d_in[idx++];   // [1024,1024]
    const float* b_proj   = (const float*)d_in[idx++];   // [1024]

    float* out = (float*)d_out;
    float* attn_out = out;                                   // [32,1024]
    float* Kout = out + BATCH * HIDDEN;                      // [32,16,2048,64]
    float* Vout = Kout + (size_t)BATCH * NUM_HEADS * T_OUT * HEAD_DIM;

    float* qkv_sym = nullptr;
    cudaGetSymbolAddress((void**)&qkv_sym, g_qkv);
    float* attn_sym = nullptr;
    cudaGetSymbolAddress((void**)&attn_sym, g_attn);

    // 1) init qkv with b_attn, attn_output region with b_proj
    init_kernel<<<(BATCH * 3 * HIDDEN + 255) / 256, 256>>>(b_attn, b_proj, attn_out);

    // 2) qkv = hs @ W_attn (+bias already in buffer)
    {
        dim3 grid(3 * HIDDEN / 128, 8);
        gemm32_kernel<<<grid, 128>>>(hs, W_attn, qkv_sym, HIDDEN, 3 * HIDDEN);
    }

    // 3) fused KV concat + attention
    attn_kernel<<<BATCH * NUM_HEADS, 256>>>(kc, vc, seq_lens, Kout, Vout);

    // 4) attn_output = g_attn @ W_proj (+bias already in buffer)
    {
        dim3 grid(HIDDEN / 128, 8);
        gemm32_kernel<<<grid, 128>>>(attn_sym, W_proj, attn_out, HIDDEN, HIDDEN);
    }
}

// round 2
// speedup vs baseline: 1.1879x; 1.1879x over previous
#include <cuda_runtime.h>
#include <cuda_bf16.h>
#include <math.h>

#define BATCH 32
#define NUM_HEADS 16
#define HEAD_DIM 64
#define HIDDEN 1024
#define T_CACHED 2047
#define T_OUT 2048
#define SCALE 0.125f   // 64^-0.5

// ---------------- device scratch (no allocations allowed) ----------------
__device__ __align__(16) float g_qkv[BATCH * 3 * HIDDEN];   // [32, 3072]
__device__ __align__(16) float g_attn[BATCH * HIDDEN];      // [32, 1024]

// ---------------- init: qkv <- b_attn broadcast, out_attn <- b_proj ----------------
__global__ void init_kernel(const float* __restrict__ b_attn,
                            const float* __restrict__ b_proj,
                            float* __restrict__ out_attn) {
    int i = blockIdx.x * 256 + threadIdx.x;
    if (i < BATCH * 3 * HIDDEN) g_qkv[i] = b_attn[i % (3 * HIDDEN)];
    if (i < BATCH * HIDDEN)     out_attn[i] = b_proj[i % HIDDEN];
}

// ---------------- small GEMM: out[32,N] += X[32,K] @ W[K,N] ----------------
// 256 threads = 128 columns x 2 batch-halves (16 accumulators each).
// K split over blockIdx.y; X chunk staged once; partials atomically merged
// into a bias-preloaded out buffer.
__global__ __launch_bounds__(256) void gemm32_kernel(const float* __restrict__ X,
                                                     const float* __restrict__ W,
                                                     float* __restrict__ out,
                                                     int K, int N) {
    const int tid = threadIdx.x;
    const int col = blockIdx.x * 128 + (tid & 127);
    const int half = tid >> 7;                  // 0 or 1: batches [0,16) or [16,32)
    const int chunk = K / gridDim.y;
    const int h0 = blockIdx.y * chunk;

    __shared__ float xs[32 * 128];              // X[hh][b], chunk <= 128

    for (int i = tid; i < 32 * chunk; i += 256) {
        int hh = i >> 5, b = i & 31;
        xs[i] = X[b * K + h0 + hh];
    }
    __syncthreads();

    float acc[16];
#pragma unroll
    for (int b = 0; b < 16; b++) acc[b] = 0.f;

    const float* xb = xs + half * 16;
#pragma unroll 4
    for (int hh = 0; hh < chunk; hh++) {
        float w = W[(size_t)(h0 + hh) * N + col];
        const float* xr = xb + hh * 32;
#pragma unroll
        for (int b = 0; b < 16; b++)
            acc[b] = fmaf(xr[b], w, acc[b]);
    }

#pragma unroll
    for (int b = 0; b < 16; b++)
        atomicAdd(&out[(size_t)(half * 16 + b) * N + col], acc[b]);
}

// ---------------- fused KV-concat + single-pass online-softmax attention ----------------
// One block per (batch, head). 256 threads: 16 groups x 16 lanes; each lane owns
// a float4 of the 64-float row. Single streaming pass over T: copy K and V rows
// to the output while accumulating online softmax (flash-style per group),
// then merge the 16 group partials.
__global__ __launch_bounds__(256)
void attn_kernel(const float* __restrict__ key_cache,
                 const float* __restrict__ value_cache,
                 const int* __restrict__ seq_lens,
                 float* __restrict__ Kout,
                 float* __restrict__ Vout) {
    const int bh = blockIdx.x;
    const int b = bh >> 4;
    const int h = bh & 15;
    const int tid = threadIdx.x;
    const int grp = tid >> 4;     // 0..15
    const int lane = tid & 15;    // 0..15

    __shared__ float sm_m[16];
    __shared__ float sm_s[16];
    __shared__ __align__(16) float4 red[16 * 16];

    const int seq_len = seq_lens[b];

    // q (scaled), plus the fresh k/v rows from the QKV GEMM
    float4 q4 = ((const float4*)(g_qkv + b * 3072 + h * HEAD_DIM))[lane];
    q4.x *= SCALE; q4.y *= SCALE; q4.z *= SCALE; q4.w *= SCALE;
    const float4 knew = ((const float4*)(g_qkv + b * 3072 + HIDDEN + h * HEAD_DIM))[lane];
    const float4 vnew = ((const float4*)(g_qkv + b * 3072 + 2 * HIDDEN + h * HEAD_DIM))[lane];

    const size_t base_c = (size_t)bh * T_CACHED * HEAD_DIM;
    const size_t base_o = (size_t)bh * T_OUT * HEAD_DIM;
    const float4* kc4 = (const float4*)(key_cache + base_c);
    const float4* vc4 = (const float4*)(value_cache + base_c);
    float4* Ko4 = (float4*)(Kout + base_o);
    float4* Vo4 = (float4*)(Vout + base_o);

    float m = -1e30f, s = 0.f;
    float4 acc = make_float4(0.f, 0.f, 0.f, 0.f);

#pragma unroll 2
    for (int t = grp; t < T_OUT; t += 16) {
        const bool cached = (t < T_CACHED);
        float4 kv = cached ? __ldcs(kc4 + (size_t)t * 16 + lane) : knew;
        float4 vv = cached ? __ldcs(vc4 + (size_t)t * 16 + lane) : vnew;
        __stcs(Ko4 + (size_t)t * 16 + lane, kv);
        __stcs(Vo4 + (size_t)t * 16 + lane, vv);

        float p = kv.x * q4.x + kv.y * q4.y + kv.z * q4.z + kv.w * q4.w;
        p += __shfl_xor_sync(0xffffffffu, p, 1);
        p += __shfl_xor_sync(0xffffffffu, p, 2);
        p += __shfl_xor_sync(0xffffffffu, p, 4);
        p += __shfl_xor_sync(0xffffffffu, p, 8);

        const bool valid = (t < seq_len) || (t == T_OUT - 1);
        if (valid) {
            if (p > m) {
                float alpha = __expf(m - p);
                s *= alpha;
                acc.x *= alpha; acc.y *= alpha; acc.z *= alpha; acc.w *= alpha;
                m = p;
            }
            float e = __expf(p - m);
            s += e;
            acc.x = fmaf(e, vv.x, acc.x);
            acc.y = fmaf(e, vv.y, acc.y);
            acc.z = fmaf(e, vv.z, acc.z);
            acc.w = fmaf(e, vv.w, acc.w);
        }
    }

    if (lane == 0) { sm_m[grp] = m; sm_s[grp] = s; }
    red[grp * 16 + lane] = acc;
    __syncthreads();

    if (tid < 16) {
        float M = -1e30f;
#pragma unroll
        for (int g = 0; g < 16; g++) M = fmaxf(M, sm_m[g]);
        float S = 0.f;
        float4 tot = make_float4(0.f, 0.f, 0.f, 0.f);
#pragma unroll
        for (int g = 0; g < 16; g++) {
            float sc = __expf(sm_m[g] - M);
            S = fmaf(sm_s[g], sc, S);
            float4 r = red[g * 16 + tid];
            tot.x = fmaf(r.x, sc, tot.x);
            tot.y = fmaf(r.y, sc, tot.y);
            tot.z = fmaf(r.z, sc, tot.z);
            tot.w = fmaf(r.w, sc, tot.w);
        }
        const float inv = 1.f / S;
        tot.x *= inv; tot.y *= inv; tot.z *= inv; tot.w *= inv;
        ((float4*)(g_attn + b * HIDDEN + h * HEAD_DIM))[tid] = tot;
    }
}

// ---------------- launch ----------------
extern "C" void kernel_launch(void* const* d_in, const int* in_sizes, int n_in,
                              void* d_out, int out_size) {
    int idx = 0;
    const float* hs       = (const float*)d_in[idx++];   // [32,1,1024]
    const float* kc       = (const float*)d_in[idx++];   // [32,16,2047,64]
    const float* vc       = (const float*)d_in[idx++];   // [32,16,2047,64]
    idx++;                                               // block_tables (unused)
    const int*   seq_lens = (const int*)d_in[idx++];     // [32]
    if (idx < n_in && in_sizes[idx] == 1) idx++;         // max_seq_len scalar, if present
    const float* W_attn   = (const float*)d_in[idx++];   // [1024,3072]
    const float* b_attn   = (const float*)d_in[idx++];   // [3072]
    const float* W_proj   = (const float*)d_in[idx++];   // [1024,1024]
    const float* b_proj   = (const float*)d_in[idx++];   // [1024]

    float* out = (float*)d_out;
    float* attn_out = out;                                   // [32,1024]
    float* Kout = out + BATCH * HIDDEN;                      // [32,16,2048,64]
    float* Vout = Kout + (size_t)BATCH * NUM_HEADS * T_OUT * HEAD_DIM;

    float* qkv_sym = nullptr;
    cudaGetSymbolAddress((void**)&qkv_sym, g_qkv);
    float* attn_sym = nullptr;
    cudaGetSymbolAddress((void**)&attn_sym, g_attn);

    // 1) seed qkv buffer with b_attn, attn_output region with b_proj
    init_kernel<<<(BATCH * 3 * HIDDEN + 255) / 256, 256>>>(b_attn, b_proj, attn_out);

    // 2) qkv += hs @ W_attn   (192 blocks, chunk=128)
    {
        dim3 grid(3 * HIDDEN / 128, 8);
        gemm32_kernel<<<grid, 256>>>(hs, W_attn, qkv_sym, HIDDEN, 3 * HIDDEN);
    }

    // 3) fused KV concat + single-pass attention
    attn_kernel<<<BATCH * NUM_HEADS, 256>>>(kc, vc, seq_lens, Kout, Vout);

    // 4) attn_output += g_attn @ W_proj   (128 blocks, chunk=64)
    {
        dim3 grid(HIDDEN / 128, 16);
        gemm32_kernel<<<grid, 256>>>(attn_sym, W_proj, attn_out, HIDDEN, HIDDEN);
    }
}

// round 3
// speedup vs baseline: 1.1892x; 1.0010x over previous
#include <cuda_runtime.h>
#include <cuda_bf16.h>
#include <math.h>

#define BATCH 32
#define NUM_HEADS 16
#define HEAD_DIM 64
#define HIDDEN 1024
#define T_CACHED 2047
#define T_OUT 2048
#define T_HALF 1024
#define SCALE 0.125f   // 64^-0.5
#define NBH (BATCH * NUM_HEADS)

// ---------------- device scratch ----------------
__device__ __align__(16) float g_qkv[BATCH * 3 * HIDDEN];     // [32, 3072]
__device__ __align__(16) float g_attn[BATCH * HIDDEN];        // [32, 1024]
__device__ float g_pm[NBH * 2];                               // per-part max
__device__ float g_ps[NBH * 2];                               // per-part sum
__device__ __align__(16) float4 g_pacc[NBH * 2][16];          // per-part unnormalized acc

// ---------------- init: qkv <- b_attn broadcast, out_attn <- b_proj ----------------
__global__ void init_kernel(const float* __restrict__ b_attn,
                            const float* __restrict__ b_proj,
                            float* __restrict__ out_attn) {
    int i = blockIdx.x * 256 + threadIdx.x;
    if (i < BATCH * 3 * HIDDEN) g_qkv[i] = b_attn[i % (3 * HIDDEN)];
    if (i < BATCH * HIDDEN)     out_attn[i] = b_proj[i % HIDDEN];
}

// ---------------- small GEMM: out[32,N] += X[32,K] @ W[K,N] ----------------
// 256 threads = 64 col-groups (4 cols each, float4 W loads) x 4 batch-quarters
// (8 batches each). Block covers 256 columns. K split over blockIdx.y.
template<int CHUNK>
__global__ __launch_bounds__(256) void gemm32_kernel(const float* __restrict__ X,
                                                     const float* __restrict__ W,
                                                     float* __restrict__ out,
                                                     int K, int N) {
    const int tid = threadIdx.x;
    const int cg = tid & 63;            // col group: 4 cols
    const int q = tid >> 6;             // batch quarter: 8 batches
    const int col0 = blockIdx.x * 256 + cg * 4;
    const int h0 = blockIdx.y * CHUNK;

    __shared__ float xs[CHUNK][32];
    for (int i = tid; i < CHUNK * 32; i += 256) {
        int hh = i >> 5, b = i & 31;
        xs[hh][b] = X[b * K + h0 + hh];
    }
    __syncthreads();

    float4 acc[8];
#pragma unroll
    for (int b = 0; b < 8; b++) acc[b] = make_float4(0.f, 0.f, 0.f, 0.f);

    const float4* W4 = (const float4*)W;
    const int n4 = N >> 2;
#pragma unroll 4
    for (int hh = 0; hh < CHUNK; hh++) {
        float4 w = __ldg(&W4[(size_t)(h0 + hh) * n4 + (col0 >> 2)]);
#pragma unroll
        for (int b = 0; b < 8; b++) {
            float x = xs[hh][q * 8 + b];
            acc[b].x = fmaf(x, w.x, acc[b].x);
            acc[b].y = fmaf(x, w.y, acc[b].y);
            acc[b].z = fmaf(x, w.z, acc[b].z);
            acc[b].w = fmaf(x, w.w, acc[b].w);
        }
    }

#pragma unroll
    for (int b = 0; b < 8; b++) {
        float* o = &out[(size_t)(q * 8 + b) * N + col0];
        atomicAdd(o + 0, acc[b].x);
        atomicAdd(o + 1, acc[b].y);
        atomicAdd(o + 2, acc[b].z);
        atomicAdd(o + 3, acc[b].w);
    }
}

// ---------------- fused KV-concat + split-T online-softmax attention ----------------
// grid = NBH*2. Each block handles one (batch, head) and half the T range.
// 256 threads: 16 groups x 16 lanes; lane owns a float4 of the 64-float row.
// Streams K/V rows: copies to output, accumulates online softmax; stores
// unnormalized partial (m, s, acc) for the merge kernel.
__global__ __launch_bounds__(256)
void attn_part_kernel(const float* __restrict__ key_cache,
                      const float* __restrict__ value_cache,
                      const int* __restrict__ seq_lens,
                      float* __restrict__ Kout,
                      float* __restrict__ Vout) {
    const int bx = blockIdx.x;
    const int bh = bx >> 1;
    const int part = bx & 1;
    const int b = bh >> 4;
    const int h = bh & 15;
    const int tid = threadIdx.x;
    const int grp = tid >> 4;
    const int lane = tid & 15;

    __shared__ float sm_m[16];
    __shared__ float sm_s[16];
    __shared__ __align__(16) float4 red[16 * 16];

    const int seq_len = seq_lens[b];
    const int t0 = part * T_HALF;
    const int t1 = t0 + T_HALF;

    float4 q4 = ((const float4*)(g_qkv + b * 3072 + h * HEAD_DIM))[lane];
    q4.x *= SCALE; q4.y *= SCALE; q4.z *= SCALE; q4.w *= SCALE;
    const float4 knew = ((const float4*)(g_qkv + b * 3072 + HIDDEN + h * HEAD_DIM))[lane];
    const float4 vnew = ((const float4*)(g_qkv + b * 3072 + 2 * HIDDEN + h * HEAD_DIM))[lane];

    const size_t base_c = (size_t)bh * T_CACHED * HEAD_DIM;
    const size_t base_o = (size_t)bh * T_OUT * HEAD_DIM;
    const float4* kc4 = (const float4*)(key_cache + base_c);
    const float4* vc4 = (const float4*)(value_cache + base_c);
    float4* Ko4 = (float4*)(Kout + base_o);
    float4* Vo4 = (float4*)(Vout + base_o);

    float m = -1e30f, s = 0.f;
    float4 acc = make_float4(0.f, 0.f, 0.f, 0.f);

#pragma unroll 2
    for (int t = t0 + grp; t < t1; t += 16) {
        const bool cached = (t < T_CACHED);
        float4 kv = cached ? __ldcs(kc4 + (size_t)t * 16 + lane) : knew;
        float4 vv = cached ? __ldcs(vc4 + (size_t)t * 16 + lane) : vnew;
        __stcs(Ko4 + (size_t)t * 16 + lane, kv);
        __stcs(Vo4 + (size_t)t * 16 + lane, vv);

        float p = kv.x * q4.x + kv.y * q4.y + kv.z * q4.z + kv.w * q4.w;
        p += __shfl_xor_sync(0xffffffffu, p, 1);
        p += __shfl_xor_sync(0xffffffffu, p, 2);
        p += __shfl_xor_sync(0xffffffffu, p, 4);
        p += __shfl_xor_sync(0xffffffffu, p, 8);

        const bool valid = (t < seq_len) || (t == T_OUT - 1);
        if (valid) {
            if (p > m) {
                float alpha = __expf(m - p);
                s *= alpha;
                acc.x *= alpha; acc.y *= alpha; acc.z *= alpha; acc.w *= alpha;
                m = p;
            }
            float e = __expf(p - m);
            s += e;
            acc.x = fmaf(e, vv.x, acc.x);
            acc.y = fmaf(e, vv.y, acc.y);
            acc.z = fmaf(e, vv.z, acc.z);
            acc.w = fmaf(e, vv.w, acc.w);
        }
    }

    if (lane == 0) { sm_m[grp] = m; sm_s[grp] = s; }
    red[grp * 16 + lane] = acc;
    __syncthreads();

    if (tid < 16) {
        float M = -1e30f;
#pragma unroll
        for (int g = 0; g < 16; g++) M = fmaxf(M, sm_m[g]);
        float S = 0.f;
        float4 tot = make_float4(0.f, 0.f, 0.f, 0.f);
#pragma unroll
        for (int g = 0; g < 16; g++) {
            float sc = __expf(sm_m[g] - M);
            S = fmaf(sm_s[g], sc, S);
            float4 r = red[g * 16 + tid];
            tot.x = fmaf(r.x, sc, tot.x);
            tot.y = fmaf(r.y, sc, tot.y);
            tot.z = fmaf(r.z, sc, tot.z);
            tot.w = fmaf(r.w, sc, tot.w);
        }
        g_pacc[bx][tid] = tot;
        if (tid == 0) { g_pm[bx] = M; g_ps[bx] = S; }
    }
}

// ---------------- merge the two T-halves per (batch, head) ----------------
__global__ __launch_bounds__(256) void attn_merge_kernel() {
    int gid = blockIdx.x * 256 + threadIdx.x;   // 512 bh * 16 lanes = 8192
    if (gid >= NBH * 16) return;
    int bh = gid >> 4;
    int lane = gid & 15;

    float m0 = g_pm[bh * 2], m1 = g_pm[bh * 2 + 1];
    float M = fmaxf(m0, m1);
    float e0 = __expf(m0 - M), e1 = __expf(m1 - M);
    float S = g_ps[bh * 2] * e0 + g_ps[bh * 2 + 1] * e1;
    float4 a0 = g_pacc[bh * 2][lane];
    float4 a1 = g_pacc[bh * 2 + 1][lane];
    float inv = 1.f / S;
    float4 r;
    r.x = (a0.x * e0 + a1.x * e1) * inv;
    r.y = (a0.y * e0 + a1.y * e1) * inv;
    r.z = (a0.z * e0 + a1.z * e1) * inv;
    r.w = (a0.w * e0 + a1.w * e1) * inv;
    int b = bh >> 4, h = bh & 15;
    ((float4*)(g_attn + b * HIDDEN + h * HEAD_DIM))[lane] = r;
}

// ---------------- launch ----------------
extern "C" void kernel_launch(void* const* d_in, const int* in_sizes, int n_in,
                              void* d_out, int out_size) {
    int idx = 0;
    const float* hs       = (const float*)d_in[idx++];   // [32,1,1024]
    const float* kc       = (const float*)d_in[idx++];   // [32,16,2047,64]
    const float* vc       = (const float*)d_in[idx++];   // [32,16,2047,64]
    idx++;                                               // block_tables (unused)
    const int*   seq_lens = (const int*)d_in[idx++];     // [32]
    if (idx < n_in && in_sizes[idx] == 1) idx++;         // max_seq_len scalar, if present
    const float* W_attn   = (const float*)d_in[idx++];   // [1024,3072]
    const float* b_attn   = (const float*)d_in[idx++];   // [3072]
    const float* W_proj   = (const float*)d_in[idx++];   // [1024,1024]
    const float* b_proj   = (const float*)d_in[idx++];   // [1024]

    float* out = (float*)d_out;
    float* attn_out = out;                                   // [32,1024]
    float* Kout = out + BATCH * HIDDEN;                      // [32,16,2048,64]
    float* Vout = Kout + (size_t)NBH * T_OUT * HEAD_DIM;

    float* qkv_sym = nullptr;
    cudaGetSymbolAddress((void**)&qkv_sym, g_qkv);
    float* attn_sym = nullptr;
    cudaGetSymbolAddress((void**)&attn_sym, g_attn);

    // 1) seed qkv buffer with b_attn, attn_output region with b_proj
    init_kernel<<<(BATCH * 3 * HIDDEN + 255) / 256, 256>>>(b_attn, b_proj, attn_out);

    // 2) qkv += hs @ W_attn   (12 x 16 = 192 blocks)
    {
        dim3 grid(3 * HIDDEN / 256, 16);
        gemm32_kernel<64><<<grid, 256>>>(hs, W_attn, qkv_sym, HIDDEN, 3 * HIDDEN);
    }

    // 3) fused KV concat + split-T attention (1024 blocks) + merge
    attn_part_kernel<<<NBH * 2, 256>>>(kc, vc, seq_lens, Kout, Vout);
    attn_merge_kernel<<<(NBH * 16 + 255) / 256, 256>>>();

    // 4) attn_output += g_attn @ W_proj   (4 x 32 = 128 blocks)
    {
        dim3 grid(HIDDEN / 256, 32);
        gemm32_kernel<32><<<grid, 256>>>(attn_sym, W_proj, attn_out, HIDDEN, HIDDEN);
    }
}